// round 17
// baseline (speedup 1.0000x reference)
#include <cuda_runtime.h>
#include <cuda_fp16.h>
#include <cstdint>

#define NB   4
#define CIN  256
#define NSP  2304      // 48*48 tokens
#define NH   8
#define HDIM 64
#define HB   32        // NH*NB
// q pre-scale folds softmax scale AND log2(e): exp(s) == exp2(s')
#define QK_SCALE_L2E (0.125f * 1.44269504088896f)

typedef unsigned long long u64;

// Scratch (device globals — no allocations allowed)
__device__ __half g_q   [(size_t)HB * NSP * HDIM];
__device__ __half g_k   [(size_t)HB * NSP * HDIM];
__device__ __half g_v   [(size_t)HB * NSP * HDIM];   // [hb][d][n] transposed
__device__ __half g_wsrh[(size_t)4 * 512 * NSP];     // fp16 scrambled ws
__device__ __half g_wh  [(size_t)3 * NH * HDIM * CIN]; // fp16 W: [m][h][d][c]

// ---- helpers ---------------------------------------------------------------
__device__ __forceinline__ float ex2(float x) {
    float r;
    asm("ex2.approx.f32 %0, %1;" : "=f"(r) : "f"(x));
    return r;
}
__device__ __forceinline__ void mma16(float* d, const uint32_t* a,
                                      uint32_t b0, uint32_t b1) {
    asm volatile(
        "mma.sync.aligned.m16n8k16.row.col.f32.f16.f16.f32 "
        "{%0,%1,%2,%3}, {%4,%5,%6,%7}, {%8,%9}, {%0,%1,%2,%3};"
        : "+f"(d[0]), "+f"(d[1]), "+f"(d[2]), "+f"(d[3])
        : "r"(a[0]), "r"(a[1]), "r"(a[2]), "r"(a[3]), "r"(b0), "r"(b1));
}
__device__ __forceinline__ void ldsm4(uint32_t* r, uint32_t addr) {
    asm volatile(
        "ldmatrix.sync.aligned.m8n8.x4.shared.b16 {%0,%1,%2,%3}, [%4];"
        : "=r"(r[0]), "=r"(r[1]), "=r"(r[2]), "=r"(r[3]) : "r"(addr));
}
__device__ __forceinline__ uint32_t s2u(const void* p) {
    return (uint32_t)__cvta_generic_to_shared(p);
}
__device__ __forceinline__ void cp16(uint32_t smem_dst, const void* gsrc) {
    asm volatile("cp.async.cg.shared.global [%0], [%1], 16;"
                 :: "r"(smem_dst), "l"(gsrc));
}
__device__ __forceinline__ uint32_t packh2(float lo, float hi) {
    __half2 h = __floats2half2_rn(lo, hi);
    return *(uint32_t*)&h;
}

// ldmatrix per-lane offsets (words), stride S
#define LDSM_B_OFF(S, mm, rr) (((((mm) >> 1) * 8 + (rr)) * (S) + ((mm) & 1) * 4) * 4)
#define LDSM_A_OFF(S, mm, rr) (((((mm) & 1) * 8 + (rr)) * (S) + ((mm) >> 1) * 4) * 4)

// ---------------------------------------------------------------------------
// Kernel P: prepack W (fp32 -> fp16). grid (24), block 256.
// ---------------------------------------------------------------------------
__global__ void wprep_kernel(const float* __restrict__ Wq,
                             const float* __restrict__ Wk,
                             const float* __restrict__ Wv) {
    const int m = blockIdx.x / NH;
    const int h = blockIdx.x % NH;
    const float* src = (m == 0 ? Wq : (m == 1 ? Wk : Wv)) + (size_t)h * HDIM * CIN;
    uint32_t* dst = (uint32_t*)(g_wh + (size_t)(m * NH + h) * HDIM * CIN);
    const int tid = threadIdx.x;
    #pragma unroll
    for (int it = 0; it < 16; it++) {
        int idx = it * 1024 + tid * 4;
        float4 v = *(const float4*)&src[idx];
        dst[idx / 2]     = packh2(v.x, v.y);
        dst[idx / 2 + 1] = packh2(v.z, v.w);
    }
}

// ---------------------------------------------------------------------------
// Kernel A: QKV projection via fp16 m16n8k16 + ldmatrix + cp.async W stream.
// One CTA = (128-token n-tile, b, head-group of 4) -> 12 GEMMs, 512 threads.
// 16 warps: 8 row-slices (16 n each) x 2 d-halves (32 d each).
// smem: Xth [128][132w] + Wsm[2][64][132w] = 135KB, 1 CTA/SM.
// grid (18, 4, 2).
// ---------------------------------------------------------------------------
#define XSW 132
__global__ void __launch_bounds__(512, 1) qkv_kernel(const float* __restrict__ x) {
    extern __shared__ uint32_t smw[];
    uint32_t* Xth = smw;                 // [128 n][132w]
    uint32_t* Wsm = smw + 128 * XSW;     // [2][64 d][132w]

    const int n0 = blockIdx.x * 128;
    const int b  = blockIdx.y;
    const int hg = blockIdx.z;

    const float* xb = x + (size_t)b * CIN * NSP;

    const int tid  = threadIdx.x;
    const int w    = tid >> 5;           // 0..15
    const int lane = tid & 31;
    const int tig  = lane & 3;
    const int gid  = lane >> 2;
    const int l7   = lane & 7, l3 = lane >> 3;
    const int mm   = lane >> 3, rr = lane & 7;

    const int ws   = w & 7;              // row slice
    const int dh   = (w >> 3) * 32;      // d half

    const uint32_t Xu = s2u(Xth), Wu = s2u(Wsm);
    const uint32_t aoffX = LDSM_A_OFF(XSW, mm, rr);
    const uint32_t boffX = LDSM_B_OFF(XSW, mm, rr);

    // issue W tile 0 copy (fp16 prepacked, 16KB: 4 cp16/thread)
    {
        const __half* wsrc = g_wh + (size_t)(hg * 4) * HDIM * CIN;
        #pragma unroll
        for (int it = 0; it < 4; it++) {
            int idx = it * 512 + tid;
            int d = idx >> 5, c4 = idx & 31;
            cp16(s2u(&Wsm[d * XSW + c4 * 4]), wsrc + d * CIN + c4 * 8);
        }
        asm volatile("cp.async.commit_group;" ::: "memory");
    }

    // fill Xth: transpose x[c][n] -> [n][c-pair] fp16 (bank-exact)
    #pragma unroll
    for (int it = 0; it < 32; it++) {
        int a = it & 15, j = it >> 4;
        int n = l7 + 8 * a;
        int wd = l3 + 4 * w + 64 * j;
        int c = 2 * wd;
        float f0 = xb[(size_t)c * NSP + n0 + n];
        float f1 = xb[(size_t)(c + 1) * NSP + n0 + n];
        Xth[n * XSW + wd] = packh2(f0, f1);
    }

    for (int i = 0; i < 12; i++) {
        const int m = i >> 2;
        const int h = hg * 4 + (i & 3);
        const int hb = h * 4 + b;
        const float oscale = (m == 0) ? QK_SCALE_L2E : 1.0f;
        __half* out = (m == 0 ? g_q : (m == 1 ? g_k : g_v)) + (size_t)hb * NSP * HDIM;
        const int buf = i & 1;

        asm volatile("cp.async.wait_group 0;" ::: "memory");
        __syncthreads();   // W tile i ready; compute i-1 done with buf^1

        if (i + 1 < 12) {
            int m2 = (i + 1) >> 2;
            int h2 = hg * 4 + ((i + 1) & 3);
            const __half* wsrc = g_wh + (size_t)(m2 * NH + h2) * HDIM * CIN;
            uint32_t* wdst = Wsm + (buf ^ 1) * 64 * XSW;
            #pragma unroll
            for (int it = 0; it < 4; it++) {
                int idx = it * 512 + tid;
                int d = idx >> 5, c4 = idx & 31;
                cp16(s2u(&wdst[d * XSW + c4 * 4]), wsrc + d * CIN + c4 * 8);
            }
            asm volatile("cp.async.commit_group;" ::: "memory");
        }

        const uint32_t wb_u = Wu + buf * 64 * XSW * 4;

        float acc[4][4];
        #pragma unroll
        for (int nt = 0; nt < 4; nt++)
            #pragma unroll
            for (int j = 0; j < 4; j++) acc[nt][j] = 0.f;

        #pragma unroll
        for (int kc = 0; kc < 16; kc++) {
            uint32_t afr[4];
            ldsm4(afr, Xu + ((ws * 16) * XSW + kc * 8) * 4 + aoffX);
            #pragma unroll
            for (int nt2 = 0; nt2 < 2; nt2++) {
                uint32_t b4[4];
                ldsm4(b4, wb_u + ((dh + nt2 * 16) * XSW + kc * 8) * 4 + boffX);
                mma16(acc[2 * nt2],     afr, b4[0], b4[1]);
                mma16(acc[2 * nt2 + 1], afr, b4[2], b4[3]);
            }
        }

        int r0 = n0 + ws * 16 + gid;
        if (m != 2) {
            uint32_t* o0 = (uint32_t*)(out + (size_t)r0 * HDIM) + dh / 2;
            uint32_t* o1 = (uint32_t*)(out + (size_t)(r0 + 8) * HDIM) + dh / 2;
            #pragma unroll
            for (int nt = 0; nt < 4; nt++) {
                o0[nt * 4 + tig] = packh2(acc[nt][0] * oscale, acc[nt][1] * oscale);
                o1[nt * 4 + tig] = packh2(acc[nt][2] * oscale, acc[nt][3] * oscale);
            }
        } else {
            #pragma unroll
            for (int nt = 0; nt < 4; nt++) {
                int d = dh + nt * 8 + 2 * tig;
                out[(size_t)d * NSP + r0]           = __float2half(acc[nt][0]);
                out[(size_t)(d + 1) * NSP + r0]     = __float2half(acc[nt][1]);
                out[(size_t)d * NSP + r0 + 8]       = __float2half(acc[nt][2]);
                out[(size_t)(d + 1) * NSP + r0 + 8] = __float2half(acc[nt][3]);
            }
        }
    }
}

// ---------------------------------------------------------------------------
// Kernel B: fp16 m16n8k16 flash attention + ldmatrix (R16 winner, unchanged).
// grid (18, 32), block 256, dyn smem 54KB -> 2 CTA/SM.
// ---------------------------------------------------------------------------
#define KS2 36
#define VS2 36
#define PS2 36
#define NKT (NSP / 64)

__device__ __forceinline__ void attn_issue_tile(const __half* kg, const __half* vg,
                                                uint32_t* Ks, uint32_t* Vs,
                                                int kt, int buf, int tid) {
    const __half* ksrc = kg + (size_t)kt * 64 * HDIM;
    const __half* vsrc = vg + (size_t)kt * 64;
    uint32_t* kdst = Ks + buf * 64 * KS2;
    uint32_t* vdst = Vs + buf * 64 * VS2;
    #pragma unroll
    for (int it = 0; it < 2; it++) {
        int idx = it * 256 + tid;
        int row = idx >> 3, c4 = idx & 7;
        cp16(s2u(&kdst[row * KS2 + c4 * 4]), ksrc + row * HDIM + c4 * 8);
    }
    #pragma unroll
    for (int it = 0; it < 2; it++) {
        int idx = it * 256 + tid;
        int row = idx >> 3, c4 = idx & 7;
        cp16(s2u(&vdst[row * VS2 + c4 * 4]), vsrc + (size_t)row * NSP + c4 * 8);
    }
    asm volatile("cp.async.commit_group;" ::: "memory");
}

__global__ void __launch_bounds__(256, 2) attn_kernel() {
    extern __shared__ uint32_t smw[];
    uint32_t* Ks = smw;                         // [2][64][36]
    uint32_t* Vs = smw + 2 * 64 * KS2;          // [2][64][36]
    uint32_t* Ps = smw + 2 * 64 * (KS2 + VS2);  // [128][36]

    const int qt = blockIdx.x;
    const int hb = blockIdx.y;
    const int h = hb >> 2, b = hb & 3;

    const __half* qg = g_q + (size_t)hb * NSP * HDIM;
    const __half* kg = g_k + (size_t)hb * NSP * HDIM;
    const __half* vg = g_v + (size_t)hb * NSP * HDIM;

    const int tid  = threadIdx.x;
    const int w    = tid >> 5;
    const int lane = tid & 31;
    const int gid  = lane >> 2;
    const int tig  = lane & 3;
    const int rb   = w * 16;
    const int mm   = lane >> 3, rr = lane & 7;

    const uint32_t Ks_u = s2u(Ks), Vs_u = s2u(Vs), Ps_u = s2u(Ps);
    const uint32_t boffB = LDSM_B_OFF(36, mm, rr);
    const uint32_t aoffP = LDSM_A_OFF(36, mm, rr);

    attn_issue_tile(kg, vg, Ks, Vs, 0, 0, tid);

    uint32_t qa[4][4];
    {
        const uint32_t* qw0 =
            (const uint32_t*)(qg + (size_t)(qt * 128 + rb + gid) * HDIM);
        const uint32_t* qw1 = qw0 + 8 * (HDIM / 2);
        #pragma unroll
        for (int kc = 0; kc < 4; kc++) {
            qa[kc][0] = qw0[kc * 8 + tig];
            qa[kc][1] = qw1[kc * 8 + tig];
            qa[kc][2] = qw0[kc * 8 + tig + 4];
            qa[kc][3] = qw1[kc * 8 + tig + 4];
        }
    }

    float o[8][4];
    #pragma unroll
    for (int i = 0; i < 8; i++)
        #pragma unroll
        for (int j = 0; j < 4; j++) o[i][j] = 0.f;
    float sum0 = 0.f, sum1 = 0.f;

    for (int kt = 0; kt < NKT; kt++) {
        const int buf = kt & 1;
        asm volatile("cp.async.wait_group 0;" ::: "memory");
        __syncthreads();
        if (kt + 1 < NKT)
            attn_issue_tile(kg, vg, Ks, Vs, kt + 1, buf ^ 1, tid);

        const uint32_t kb_u = Ks_u + buf * 64 * KS2 * 4;
        const uint32_t vb_u = Vs_u + buf * 64 * VS2 * 4;

        float s[8][4];
        #pragma unroll
        for (int nt = 0; nt < 8; nt++)
            #pragma unroll
            for (int j = 0; j < 4; j++) s[nt][j] = 0.f;

        #pragma unroll
        for (int kc = 0; kc < 4; kc++) {
            #pragma unroll
            for (int nt2 = 0; nt2 < 4; nt2++) {
                uint32_t b4[4];
                ldsm4(b4, kb_u + (nt2 * 16 * KS2 + kc * 8) * 4 + boffB);
                mma16(s[2 * nt2],     qa[kc], b4[0], b4[1]);
                mma16(s[2 * nt2 + 1], qa[kc], b4[2], b4[3]);
            }
        }

        #pragma unroll
        for (int nt = 0; nt < 8; nt++) {
            float e0 = ex2(s[nt][0]);
            float e1 = ex2(s[nt][1]);
            float e2 = ex2(s[nt][2]);
            float e3 = ex2(s[nt][3]);
            sum0 += e0 + e1;
            sum1 += e2 + e3;
            Ps[(rb + gid) * PS2 + nt * 4 + tig]     = packh2(e0, e1);
            Ps[(rb + gid + 8) * PS2 + nt * 4 + tig] = packh2(e2, e3);
        }
        __syncwarp();

        #pragma unroll
        for (int kc = 0; kc < 4; kc++) {
            uint32_t pa[4];
            ldsm4(pa, Ps_u + (rb * PS2 + kc * 8) * 4 + aoffP);
            #pragma unroll
            for (int nt2 = 0; nt2 < 4; nt2++) {
                uint32_t v4[4];
                ldsm4(v4, vb_u + (nt2 * 16 * VS2 + kc * 8) * 4 + boffB);
                mma16(o[2 * nt2],     pa, v4[0], v4[1]);
                mma16(o[2 * nt2 + 1], pa, v4[2], v4[3]);
            }
        }
    }

    sum0 += __shfl_xor_sync(0xffffffffu, sum0, 1);
    sum0 += __shfl_xor_sync(0xffffffffu, sum0, 2);
    sum1 += __shfl_xor_sync(0xffffffffu, sum1, 1);
    sum1 += __shfl_xor_sync(0xffffffffu, sum1, 2);
    const float inv0 = 1.0f / sum0;
    const float inv1 = 1.0f / sum1;

    {
        const int n0 = qt * 128 + rb + gid;
        const int n1 = n0 + 8;
        const size_t ob0 = ((size_t)((h >> 1) * 512 + ((h & 1) << 8) + n0 / 9)) * NSP
                         + (n0 % 9) * 256 + b * 64;
        const size_t ob1 = ((size_t)((h >> 1) * 512 + ((h & 1) << 8) + n1 / 9)) * NSP
                         + (n1 % 9) * 256 + b * 64;
        uint32_t* wp = (uint32_t*)g_wsrh;
        #pragma unroll
        for (int nt = 0; nt < 8; nt++) {
            int d = nt * 8 + 2 * tig;
            wp[(ob0 + d) >> 1] = packh2(o[nt][0] * inv0, o[nt][1] * inv0);
            wp[(ob1 + d) >> 1] = packh2(o[nt][2] * inv1, o[nt][3] * inv1);
        }
    }
}

// ---------------------------------------------------------------------------
// Kernel C: output projection via fp16 m16n8k16 + ldmatrix (R16 winner).
// grid (18, 2, 4), block 256, dyn smem 36.9KB -> 2 CTA/SM.
// ---------------------------------------------------------------------------
#define XS2 36
__global__ void __launch_bounds__(256, 2) oproj_kernel(const float* __restrict__ Wo,
                             float* __restrict__ out) {
    extern __shared__ uint32_t smw[];
    uint32_t* Wos = smw;                 // [128 o][36w]
    uint32_t* Pt  = smw + 128 * XS2;     // [128 p][36w]

    const int p0 = blockIdx.x * 128;
    const int o0 = blockIdx.y * 128;
    const int b2 = blockIdx.z;
    const __half* wsr = g_wsrh + (size_t)b2 * 512 * NSP;

    const int tid  = threadIdx.x;
    const int w    = tid >> 5;
    const int lane = tid & 31;
    const int gid  = lane >> 2;
    const int tig  = lane & 3;
    const int mr0  = (w >> 1) * 32;
    const int nc0  = (w & 1) * 64;
    const int l7 = lane & 7, l3 = lane >> 3;
    const int mm = lane >> 3, rr = lane & 7;

    const uint32_t Wu = s2u(Wos), Pu = s2u(Pt);
    const uint32_t aoffO = LDSM_A_OFF(XS2, mm, rr);
    const uint32_t boffO = LDSM_B_OFF(XS2, mm, rr);

    float acc[2][8][4];
    #pragma unroll
    for (int mt = 0; mt < 2; mt++)
        #pragma unroll
        for (int nt = 0; nt < 8; nt++)
            #pragma unroll
            for (int j = 0; j < 4; j++) acc[mt][nt][j] = 0.f;

    for (int c0 = 0; c0 < 512; c0 += 64) {
        #pragma unroll
        for (int it = 0; it < 8; it++) {
            int idx = it * 256 + tid;
            int o = idx >> 4, c4 = idx & 15;
            float4 wv = *(const float4*)&Wo[(size_t)(o0 + o) * 512 + c0 + c4 * 4];
            Wos[o * XS2 + c4 * 2]     = packh2(wv.x, wv.y);
            Wos[o * XS2 + c4 * 2 + 1] = packh2(wv.z, wv.w);
        }
        #pragma unroll
        for (int it = 0; it < 16; it++) {
            int p = l7 + 8 * it;
            int wd = l3 + 4 * w;
            int c = c0 + 2 * wd;
            float f0 = __half2float(wsr[(size_t)c * NSP + p0 + p]);
            float f1 = __half2float(wsr[(size_t)(c + 1) * NSP + p0 + p]);
            Pt[p * XS2 + wd] = packh2(f0, f1);
        }
        __syncthreads();

        #pragma unroll
        for (int kc = 0; kc < 4; kc++) {
            uint32_t afr0[4], afr1[4];
            ldsm4(afr0, Wu + (mr0 * XS2 + kc * 8) * 4 + aoffO);
            ldsm4(afr1, Wu + ((mr0 + 16) * XS2 + kc * 8) * 4 + aoffO);
            #pragma unroll
            for (int nt2 = 0; nt2 < 4; nt2++) {
                uint32_t b4[4];
                ldsm4(b4, Pu + ((nc0 + nt2 * 16) * XS2 + kc * 8) * 4 + boffO);
                mma16(acc[0][2 * nt2],     afr0, b4[0], b4[1]);
                mma16(acc[0][2 * nt2 + 1], afr0, b4[2], b4[3]);
                mma16(acc[1][2 * nt2],     afr1, b4[0], b4[1]);
                mma16(acc[1][2 * nt2 + 1], afr1, b4[2], b4[3]);
            }
        }
        __syncthreads();
    }

    #pragma unroll
    for (int mt = 0; mt < 2; mt++) {
        int orow = o0 + mr0 + mt * 16 + gid;
        #pragma unroll
        for (int nt = 0; nt < 8; nt++) {
            int p = p0 + nc0 + nt * 8 + 2 * tig;
            *(float2*)&out[((size_t)(b2 * 256 + orow)) * NSP + p] =
                make_float2(acc[mt][nt][0], acc[mt][nt][1]);
            *(float2*)&out[((size_t)(b2 * 256 + orow + 8)) * NSP + p] =
                make_float2(acc[mt][nt][2], acc[mt][nt][3]);
        }
    }
}

// ---------------------------------------------------------------------------
extern "C" void kernel_launch(void* const* d_in, const int* in_sizes, int n_in,
                              void* d_out, int out_size) {
    const float* x  = (const float*)d_in[0];
    const float* Wq = (const float*)d_in[1];
    const float* Wk = (const float*)d_in[2];
    const float* Wv = (const float*)d_in[3];
    const float* Wo = (const float*)d_in[4];
    float* out = (float*)d_out;

    const int qkv_smem  = (128 * XSW + 2 * 64 * XSW) * 4;              // 135168
    const int attn_smem = (2 * 64 * KS2 + 2 * 64 * VS2 + 128 * PS2) * 4; // 55296
    const int oprj_smem = (128 * XS2 + 128 * XS2) * 4;                 // 36864

    cudaFuncSetAttribute(qkv_kernel,
                         cudaFuncAttributeMaxDynamicSharedMemorySize, qkv_smem);
    cudaFuncSetAttribute(attn_kernel,
                         cudaFuncAttributeMaxDynamicSharedMemorySize, attn_smem);
    cudaFuncSetAttribute(oproj_kernel,
                         cudaFuncAttributeMaxDynamicSharedMemorySize, oprj_smem);

    wprep_kernel<<<24, 256>>>(Wq, Wk, Wv);
    qkv_kernel<<<dim3(NSP / 128, NB, 2), 512, qkv_smem>>>(x);
    attn_kernel<<<dim3(NSP / 128, HB), 256, attn_smem>>>();
    oproj_kernel<<<dim3(NSP / 128, 2, 4), 256, oprj_smem>>>(Wo, out);
}